// round 11
// baseline (speedup 1.0000x reference)
#include <cuda_runtime.h>
#include <cstdint>

#define Bn   4
#define Cc   64
#define CIc  32
#define HMc  128
#define NCc  4096

// ---------------- helpers ----------------------------------------------------
__device__ __forceinline__ float tf32r(float x) {
    unsigned u; asm("cvt.rna.tf32.f32 %0, %1;" : "=r"(u) : "f"(x));
    return __uint_as_float(u);
}
// D += A*B, m16n8k8 tf32 (A row-major, B col-major)
__device__ __forceinline__ void mma_tf32(float* d, const unsigned* a, const unsigned* b) {
    asm volatile("mma.sync.aligned.m16n8k8.row.col.f32.tf32.tf32.f32 "
        "{%0,%1,%2,%3}, {%4,%5,%6,%7}, {%8,%9}, {%0,%1,%2,%3};"
        : "+f"(d[0]), "+f"(d[1]), "+f"(d[2]), "+f"(d[3])
        : "r"(a[0]), "r"(a[1]), "r"(a[2]), "r"(a[3]), "r"(b[0]), "r"(b[1]));
}

// ---------------- scratch globals (no allocation allowed) --------------------
__device__ float g_Q[Bn*NCc*CIc];
__device__ float g_K[Bn*NCc*CIc];
__device__ float g_V[Bn*NCc*CIc];
__device__ float g_attn[Bn*NCc*CIc];   // normalized attention output, [pix][32]
__device__ float g_vconv[Bn*Cc*NCc];
__device__ float g_stats[2*Cc];
__device__ float g_ss[2*Cc];

__global__ void zero_k() {
    if (threadIdx.x < 2*Cc) g_stats[threadIdx.x] = 0.f;
}

// g(cross) -> Q, theta(cross) -> K  (tf32-rounded, [b*Nc+p][32] rows)
__global__ void proj_cross_k(const float* __restrict__ cross,
                             const float* __restrict__ gw, const float* __restrict__ gb,
                             const float* __restrict__ tw, const float* __restrict__ tb) {
    __shared__ float swg[CIc*Cc];
    __shared__ float swt[CIc*Cc];
    int tid = threadIdx.x;
    for (int i = tid; i < CIc*Cc; i += 128) { swg[i] = gw[i]; swt[i] = tw[i]; }
    __syncthreads();
    int pix = blockIdx.x*128 + tid;
    int b = pix >> 12, p = pix & (NCc-1);
    float q[CIc], k[CIc];
    #pragma unroll
    for (int o = 0; o < CIc; o++) { q[o] = gb[o]; k[o] = tb[o]; }
    const float* cp = cross + (size_t)b*Cc*NCc + p;
    for (int c = 0; c < Cc; c++) {
        float v = cp[(size_t)c*NCc];
        #pragma unroll
        for (int o = 0; o < CIc; o++) { q[o] += swg[o*Cc+c]*v; k[o] += swt[o*Cc+c]*v; }
    }
    float* qo = g_Q + (size_t)pix*CIc;
    float* ko = g_K + (size_t)pix*CIc;
    #pragma unroll
    for (int o = 0; o < CIc; o++) { qo[o] = tf32r(q[o]); ko[o] = tf32r(k[o]); }
}

// phi(bilinear-downsample(main)) -> V (tf32-rounded, pixel-major rows of 32).
__global__ void proj_main_k(const float* __restrict__ mainf,
                            const float* __restrict__ pw, const float* __restrict__ pb) {
    __shared__ float swp[CIc*Cc];
    int tid = threadIdx.x;
    for (int i = tid; i < CIc*Cc; i += 128) swp[i] = pw[i];
    __syncthreads();
    int pix = blockIdx.x*128 + tid;
    int b = pix >> 12, p = pix & (NCc-1);
    int i = p >> 6, j = p & 63;
    float a[CIc];
    #pragma unroll
    for (int o = 0; o < CIc; o++) a[o] = pb[o];
    const float* mp = mainf + (size_t)b*Cc*HMc*HMc + (2*i)*HMc + 2*j;
    for (int c = 0; c < Cc; c++) {
        const float* m = mp + (size_t)c*HMc*HMc;
        float v = 0.25f*(m[0] + m[1] + m[HMc] + m[HMc+1]);
        #pragma unroll
        for (int o = 0; o < CIc; o++) a[o] += swp[o*Cc+c]*v;
    }
    float* vo = g_V + (size_t)pix*CIc;
    #pragma unroll
    for (int o = 0; o < CIc; o++) vo[o] = tf32r(a[o]);
}

// ---------------- tensor-core attention (mma.sync tf32) ----------------------
// CTA = 64-query tile x batch, 4 warps x 16-row strips (small CTA => 3 CTAs/SM,
// one wave of 256 CTAs). Per 128-key tile:
//   S = Q@K^T (mma), P = exp(S) (regs), P round-trip via warp-private smem,
//   O += P@V (mma). Unnormalized accumulation across ALL key tiles (logits are
//   O(1): no max subtraction needed), l summed per row, normalize at the end.
// smem word-offset layout (fragment-paired, conflict-free strides):
#define KSTR 40
#define VSTR 72
#define PSTR 132
#define SM_K 0
#define SM_V (128*KSTR)                 // 5120
#define SM_P (SM_V + 64*VSTR)           // 9728
#define ATTN_SMEM ((SM_P + 64*PSTR)*4)  // 72704 bytes

__global__ void __launch_bounds__(128, 3) attn_tc_k() {
    extern __shared__ float sm[];
    int tid = threadIdx.x, lane = tid & 31, w = tid >> 5;
    int gq = lane >> 2, gj = lane & 3;
    int b = blockIdx.y, qbase = blockIdx.x*64;

    // Q fragments: rows 16w+gq, 16w+gq+8; 4 k-chunks of 8
    unsigned qa[4][4];
    {
        const float* Qb = g_Q + ((size_t)(b*NCc + qbase + 16*w))*CIc;
        #pragma unroll
        for (int kc = 0; kc < 4; kc++) {
            qa[kc][0] = __float_as_uint(Qb[gq*32     + 8*kc + gj]);
            qa[kc][1] = __float_as_uint(Qb[(gq+8)*32 + 8*kc + gj]);
            qa[kc][2] = __float_as_uint(Qb[gq*32     + 8*kc + gj + 4]);
            qa[kc][3] = __float_as_uint(Qb[(gq+8)*32 + 8*kc + gj + 4]);
        }
    }

    float O[4][4];
    #pragma unroll
    for (int n = 0; n < 4; n++) { O[n][0]=O[n][1]=O[n][2]=O[n][3]=0.f; }
    float la = 0.f, lb = 0.f;

    int r = tid;   // fill: key row r, both column halves
    for (int t = 0; t < 32; t++) {
        __syncthreads();   // previous tile fully consumed
        // K tile -> fragment-paired layout: K'[key][kc*8 + (c&3)*2 + (c>>2 within chunk)]
        // V tile -> key-paired layout: V'[(kc*4+gj)][ch*2 + (key&7)>>2]
        {
            const float4* ks = reinterpret_cast<const float4*>(
                g_K + ((size_t)(b*NCc + t*128 + r))*CIc);
            const float4* vs = reinterpret_cast<const float4*>(
                g_V + ((size_t)(b*NCc + t*128 + r))*CIc);
            int vbase = SM_V + ((r>>3)*4 + (r&3))*VSTR + ((r&7)>>2);
            #pragma unroll
            for (int i = 0; i < 8; i++) {
                float4 k4 = ks[i];
                float kv[4] = {k4.x, k4.y, k4.z, k4.w};
                #pragma unroll
                for (int u = 0; u < 4; u++) {
                    int c = 4*i + u;
                    sm[SM_K + r*KSTR + (c>>3)*8 + (c&3)*2 + ((c&7)>>2)] = kv[u];
                }
                float4 v4 = vs[i];
                int c0 = 4*i;
                sm[vbase + (c0+0)*2] = v4.x;
                sm[vbase + (c0+1)*2] = v4.y;
                sm[vbase + (c0+2)*2] = v4.z;
                sm[vbase + (c0+3)*2] = v4.w;
            }
        }
        __syncthreads();

        // QK: 16 n-tiles of 8 keys, k = 32 (4 chunks)
        float S[16][4];
        #pragma unroll
        for (int n = 0; n < 16; n++) {
            S[n][0]=S[n][1]=S[n][2]=S[n][3]=0.f;
            const float* kr = sm + SM_K + (8*n + gq)*KSTR + gj*2;
            #pragma unroll
            for (int kc = 0; kc < 4; kc++) {
                uint2 kb = *reinterpret_cast<const uint2*>(kr + kc*8);
                unsigned bb[2] = {kb.x, kb.y};
                mma_tf32(S[n], qa[kc], bb);
            }
        }
        // exp + warp-private P store
        #pragma unroll
        for (int n = 0; n < 16; n++) {
            float e0 = __expf(S[n][0]), e1 = __expf(S[n][1]);
            float e2 = __expf(S[n][2]), e3 = __expf(S[n][3]);
            la += e0 + e1; lb += e2 + e3;
            int col = 8*n + 2*gj;
            *reinterpret_cast<float2*>(sm + SM_P + (16*w+gq)*PSTR + col) =
                make_float2(tf32r(e0), tf32r(e1));
            *reinterpret_cast<float2*>(sm + SM_P + (16*w+gq+8)*PSTR + col) =
                make_float2(tf32r(e2), tf32r(e3));
        }
        __syncwarp();
        // PV: O[16x32] += P[16x128] @ V[128x32]
        const float* Pr0 = sm + SM_P + (16*w+gq)*PSTR + gj;
        #pragma unroll
        for (int kc = 0; kc < 16; kc++) {
            unsigned pa[4];
            pa[0] = __float_as_uint(Pr0[kc*8]);
            pa[1] = __float_as_uint(Pr0[8*PSTR + kc*8]);
            pa[2] = __float_as_uint(Pr0[kc*8 + 4]);
            pa[3] = __float_as_uint(Pr0[8*PSTR + kc*8 + 4]);
            const float* vr = sm + SM_V + (kc*4+gj)*VSTR + gq*2;
            #pragma unroll
            for (int n = 0; n < 4; n++) {
                uint2 vb = *reinterpret_cast<const uint2*>(vr + 16*n);
                unsigned bb[2] = {vb.x, vb.y};
                mma_tf32(O[n], pa, bb);
            }
        }
    }
    // row sums: reduce over the 4 lanes of each quad
    la += __shfl_xor_sync(0xffffffffu, la, 1);
    la += __shfl_xor_sync(0xffffffffu, la, 2);
    lb += __shfl_xor_sync(0xffffffffu, lb, 1);
    lb += __shfl_xor_sync(0xffffffffu, lb, 2);
    float ia = 1.f/la, ib = 1.f/lb;
    int row0 = qbase + 16*w + gq;
    float* dst = g_attn + ((size_t)b*NCc)*CIc;
    #pragma unroll
    for (int n = 0; n < 4; n++) {
        int col = 8*n + 2*gj;
        *reinterpret_cast<float2*>(dst + (size_t)row0*32 + col) =
            make_float2(O[n][0]*ia, O[n][1]*ia);
        *reinterpret_cast<float2*>(dst + (size_t)(row0+8)*32 + col) =
            make_float2(O[n][2]*ib, O[n][3]*ib);
    }
}

// Apply W (1x1 conv 32->64), coalesced channel-major write, BN batch stats.
__global__ void reduce_conv_k(const float* __restrict__ ww, const float* __restrict__ wb) {
    __shared__ float sw[Cc*CIc];
    __shared__ float stage[Cc*129];
    int tid = threadIdx.x;
    for (int i = tid; i < Cc*CIc; i += 128) sw[i] = ww[i];
    __syncthreads();
    int pix = blockIdx.x*128 + tid;
    int b = pix >> 12;

    float a[CIc];
    {
        const float4* pa = reinterpret_cast<const float4*>(g_attn + (size_t)pix*CIc);
        #pragma unroll
        for (int u = 0; u < 8; u++) {
            float4 v = pa[u];
            a[4*u+0] = v.x; a[4*u+1] = v.y; a[4*u+2] = v.z; a[4*u+3] = v.w;
        }
    }
    for (int o = 0; o < Cc; o++) {
        float t = wb[o];
        #pragma unroll
        for (int c = 0; c < CIc; c++) t += sw[o*CIc+c]*a[c];
        stage[o*129 + tid] = t;
    }
    __syncthreads();
    int pblock = (blockIdx.x*128) & (NCc-1);
    float* vout = g_vconv + (size_t)b*Cc*NCc + pblock;
    for (int idx = tid; idx < Cc*128; idx += 128) {
        int o = idx >> 7, pl = idx & 127;
        vout[(size_t)o*NCc + pl] = stage[o*129 + pl];
    }
    if (tid < Cc) {
        float s1 = 0.f, s2 = 0.f;
        for (int pl = 0; pl < 128; pl++) {
            float v = stage[tid*129 + pl];
            s1 += v; s2 += v*v;
        }
        atomicAdd(&g_stats[tid], s1);
        atomicAdd(&g_stats[Cc+tid], s2);
    }
}

__global__ void finalize_k(const float* __restrict__ gamma, const float* __restrict__ beta) {
    int o = threadIdx.x;
    if (o < Cc) {
        float ninv = 1.f/(float)(Bn*NCc);
        float mean = g_stats[o]*ninv;
        float var  = g_stats[Cc+o]*ninv - mean*mean;
        float sc   = gamma[o]*rsqrtf(var + 1e-5f);
        g_ss[o]    = sc;
        g_ss[Cc+o] = beta[o] - mean*sc;
    }
}

// BN folded into upsample: out = sc*bilerp(vconv) + sh + main
__global__ void upsample_k(const float* __restrict__ mainf, float* __restrict__ out) {
    int idx = blockIdx.x*256 + threadIdx.x;
    int j = idx & 127, i = (idx >> 7) & 127, o = (idx >> 14) & 63, b = idx >> 20;
    float si = fminf(fmaxf((i+0.5f)*0.5f - 0.5f, 0.f), 63.f);
    float sj = fminf(fmaxf((j+0.5f)*0.5f - 0.5f, 0.f), 63.f);
    int i0 = (int)si; int i1 = min(i0+1, 63); float wi = si - (float)i0;
    int j0 = (int)sj; int j1 = min(j0+1, 63); float wj = sj - (float)j0;
    const float* vb = g_vconv + ((size_t)(b*Cc + o))*NCc;
    float v00 = vb[i0*64 + j0], v01 = vb[i0*64 + j1];
    float v10 = vb[i1*64 + j0], v11 = vb[i1*64 + j1];
    float v = (v00*(1.f-wj) + v01*wj)*(1.f-wi) + (v10*(1.f-wj) + v11*wj)*wi;
    out[idx] = v*g_ss[o] + g_ss[Cc+o] + mainf[idx];
}

extern "C" void kernel_launch(void* const* d_in, const int* in_sizes, int n_in,
                              void* d_out, int out_size) {
    const float* mainf   = (const float*)d_in[0];
    const float* crossf  = (const float*)d_in[1];
    const float* g_w     = (const float*)d_in[2];
    const float* g_b     = (const float*)d_in[3];
    const float* theta_w = (const float*)d_in[4];
    const float* theta_b = (const float*)d_in[5];
    const float* phi_w   = (const float*)d_in[6];
    const float* phi_b   = (const float*)d_in[7];
    const float* w_w     = (const float*)d_in[8];
    const float* w_b     = (const float*)d_in[9];
    const float* bn_g    = (const float*)d_in[10];
    const float* bn_b    = (const float*)d_in[11];
    float* out = (float*)d_out;

    cudaFuncSetAttribute(attn_tc_k, cudaFuncAttributeMaxDynamicSharedMemorySize, ATTN_SMEM);

    zero_k<<<1, 128>>>();
    proj_cross_k<<<Bn*NCc/128, 128>>>(crossf, g_w, g_b, theta_w, theta_b);
    proj_main_k<<<Bn*NCc/128, 128>>>(mainf, phi_w, phi_b);
    attn_tc_k<<<dim3(NCc/64, Bn), 128, ATTN_SMEM>>>();
    reduce_conv_k<<<Bn*NCc/128, 128>>>(w_w, w_b);
    finalize_k<<<1, 64>>>(bn_g, bn_b);
    upsample_k<<<(Bn*Cc*HMc*HMc)/256, 256>>>(mainf, out);
}

// round 12
// speedup vs baseline: 1.5624x; 1.5624x over previous
#include <cuda_runtime.h>
#include <cstdint>

#define Bn   4
#define Cc   64
#define CIc  32
#define HMc  128
#define NCc  4096
#define SPL  2          // split-K factor
#define TK   64         // keys per tile

// ---------------- helpers ----------------------------------------------------
__device__ __forceinline__ float tf32r(float x) {
    unsigned u; asm("cvt.rna.tf32.f32 %0, %1;" : "=r"(u) : "f"(x));
    return __uint_as_float(u);
}
// D += A*B, m16n8k8 tf32 (A row-major, B col-major)
__device__ __forceinline__ void mma_tf32(float* d, const unsigned* a, const unsigned* b) {
    asm volatile("mma.sync.aligned.m16n8k8.row.col.f32.tf32.tf32.f32 "
        "{%0,%1,%2,%3}, {%4,%5,%6,%7}, {%8,%9}, {%0,%1,%2,%3};"
        : "+f"(d[0]), "+f"(d[1]), "+f"(d[2]), "+f"(d[3])
        : "r"(a[0]), "r"(a[1]), "r"(a[2]), "r"(a[3]), "r"(b[0]), "r"(b[1]));
}

// ---------------- scratch globals (no allocation allowed) --------------------
__device__ float g_Q[Bn*NCc*CIc];
__device__ float g_K[Bn*NCc*CIc];
__device__ float g_V[Bn*NCc*CIc];
__device__ float g_Pacc[Bn*SPL*NCc*CIc];   // unnormalized split-K partial O
__device__ float g_Pl[Bn*SPL*NCc];         // split-K partial row sums
__device__ float g_vconv[Bn*Cc*NCc];
__device__ float g_stats[2*Cc];
__device__ float g_ss[2*Cc];

__global__ void zero_k() {
    if (threadIdx.x < 2*Cc) g_stats[threadIdx.x] = 0.f;
}

// g(cross) -> Q, theta(cross) -> K  (tf32-rounded, [b*Nc+p][32] rows)
__global__ void proj_cross_k(const float* __restrict__ cross,
                             const float* __restrict__ gw, const float* __restrict__ gb,
                             const float* __restrict__ tw, const float* __restrict__ tb) {
    __shared__ float swg[CIc*Cc];
    __shared__ float swt[CIc*Cc];
    int tid = threadIdx.x;
    for (int i = tid; i < CIc*Cc; i += 128) { swg[i] = gw[i]; swt[i] = tw[i]; }
    __syncthreads();
    int pix = blockIdx.x*128 + tid;
    int b = pix >> 12, p = pix & (NCc-1);
    float q[CIc], k[CIc];
    #pragma unroll
    for (int o = 0; o < CIc; o++) { q[o] = gb[o]; k[o] = tb[o]; }
    const float* cp = cross + (size_t)b*Cc*NCc + p;
    for (int c = 0; c < Cc; c++) {
        float v = cp[(size_t)c*NCc];
        #pragma unroll
        for (int o = 0; o < CIc; o++) { q[o] += swg[o*Cc+c]*v; k[o] += swt[o*Cc+c]*v; }
    }
    float* qo = g_Q + (size_t)pix*CIc;
    float* ko = g_K + (size_t)pix*CIc;
    #pragma unroll
    for (int o = 0; o < CIc; o++) { qo[o] = tf32r(q[o]); ko[o] = tf32r(k[o]); }
}

// phi(bilinear-downsample(main)) -> V (tf32-rounded, pixel-major rows of 32).
__global__ void proj_main_k(const float* __restrict__ mainf,
                            const float* __restrict__ pw, const float* __restrict__ pb) {
    __shared__ float swp[CIc*Cc];
    int tid = threadIdx.x;
    for (int i = tid; i < CIc*Cc; i += 128) swp[i] = pw[i];
    __syncthreads();
    int pix = blockIdx.x*128 + tid;
    int b = pix >> 12, p = pix & (NCc-1);
    int i = p >> 6, j = p & 63;
    float a[CIc];
    #pragma unroll
    for (int o = 0; o < CIc; o++) a[o] = pb[o];
    const float* mp = mainf + (size_t)b*Cc*HMc*HMc + (2*i)*HMc + 2*j;
    for (int c = 0; c < Cc; c++) {
        const float* m = mp + (size_t)c*HMc*HMc;
        float v = 0.25f*(m[0] + m[1] + m[HMc] + m[HMc+1]);
        #pragma unroll
        for (int o = 0; o < CIc; o++) a[o] += swp[o*Cc+c]*v;
    }
    float* vo = g_V + (size_t)pix*CIc;
    #pragma unroll
    for (int o = 0; o < CIc; o++) vo[o] = tf32r(a[o]);
}

// ---------------- tensor-core attention (mma.sync tf32) ----------------------
// CTA = 128-query tile x split x batch; 8 warps x 16-row strips; TK=64 keys/tile.
// Small tile (S[8][4]) + 54KB smem => 2 CTAs/SM; split-K=2 => 256 CTAs fill chip.
// Per tile: S = Q@K^T (mma), P = exp(S), P via warp-private smem, O += P@V (mma).
// Unnormalized accumulation (logits O(1): no max), partials merged in reduce.
// smem word-offset layout (fragment-paired, conflict-free strides):
#define KSTR 40
#define VSTR 72
#define PSTR 68
#define SM_K 0
#define SM_V (TK*KSTR)                  // 2560
#define SM_P (SM_V + 32*VSTR)           // 4864
#define ATTN_SMEM ((SM_P + 128*PSTR)*4) // 54272 bytes

__global__ void __launch_bounds__(256, 2) attn_tc_k() {
    extern __shared__ float sm[];
    int tid = threadIdx.x, lane = tid & 31, w = tid >> 5;
    int gq = lane >> 2, gj = lane & 3;
    int b = blockIdx.z, s = blockIdx.y, qbase = blockIdx.x*128;

    // Q fragments: rows 16w+gq, 16w+gq+8; 4 k-chunks of 8
    unsigned qa[4][4];
    {
        const float* Qb = g_Q + ((size_t)(b*NCc + qbase + 16*w))*CIc;
        #pragma unroll
        for (int kc = 0; kc < 4; kc++) {
            qa[kc][0] = __float_as_uint(Qb[gq*32     + 8*kc + gj]);
            qa[kc][1] = __float_as_uint(Qb[(gq+8)*32 + 8*kc + gj]);
            qa[kc][2] = __float_as_uint(Qb[gq*32     + 8*kc + gj + 4]);
            qa[kc][3] = __float_as_uint(Qb[(gq+8)*32 + 8*kc + gj + 4]);
        }
    }

    float O[4][4];
    #pragma unroll
    for (int n = 0; n < 4; n++) { O[n][0]=O[n][1]=O[n][2]=O[n][3]=0.f; }
    float la = 0.f, lb = 0.f;

    int r = tid >> 2, q4 = tid & 3;   // fill: key row r, column quarter q4
    int keybase = b*NCc + s*(NCc/SPL);
    for (int t = 0; t < (NCc/SPL)/TK; t++) {
        __syncthreads();   // previous tile fully consumed
        // K tile -> fragment-paired: K'[key][kc*8 + (c&3)*2 + ((c&7)>>2)]
        // V tile -> key-paired:      V'[(kc*4+gjv)][ch*2 + (key&7)>>2]
        {
            const float4* ks = reinterpret_cast<const float4*>(
                g_K + ((size_t)(keybase + t*TK + r))*CIc);
            const float4* vs = reinterpret_cast<const float4*>(
                g_V + ((size_t)(keybase + t*TK + r))*CIc);
            int vbase = SM_V + ((r>>3)*4 + (r&3))*VSTR + ((r&7)>>2);
            #pragma unroll
            for (int h = 0; h < 2; h++) {
                float4 k4 = ks[q4*2 + h];
                float kv[4] = {k4.x, k4.y, k4.z, k4.w};
                #pragma unroll
                for (int u = 0; u < 4; u++) {
                    int c = q4*8 + h*4 + u;
                    sm[SM_K + r*KSTR + (c>>3)*8 + (c&3)*2 + ((c&7)>>2)] = kv[u];
                }
                float4 v4 = vs[q4*2 + h];
                int c0 = q4*8 + h*4;
                sm[vbase + (c0+0)*2] = v4.x;
                sm[vbase + (c0+1)*2] = v4.y;
                sm[vbase + (c0+2)*2] = v4.z;
                sm[vbase + (c0+3)*2] = v4.w;
            }
        }
        __syncthreads();

        // QK: 8 n-tiles of 8 keys, k = 32 (4 chunks)
        float S[8][4];
        #pragma unroll
        for (int n = 0; n < 8; n++) {
            S[n][0]=S[n][1]=S[n][2]=S[n][3]=0.f;
            const float* kr = sm + SM_K + (8*n + gq)*KSTR + gj*2;
            #pragma unroll
            for (int kc = 0; kc < 4; kc++) {
                uint2 kb = *reinterpret_cast<const uint2*>(kr + kc*8);
                unsigned bb[2] = {kb.x, kb.y};
                mma_tf32(S[n], qa[kc], bb);
            }
        }
        // exp + warp-private P store
        #pragma unroll
        for (int n = 0; n < 8; n++) {
            float e0 = __expf(S[n][0]), e1 = __expf(S[n][1]);
            float e2 = __expf(S[n][2]), e3 = __expf(S[n][3]);
            la += e0 + e1; lb += e2 + e3;
            int col = 8*n + 2*gj;
            *reinterpret_cast<float2*>(sm + SM_P + (16*w+gq)*PSTR + col) =
                make_float2(tf32r(e0), tf32r(e1));
            *reinterpret_cast<float2*>(sm + SM_P + (16*w+gq+8)*PSTR + col) =
                make_float2(tf32r(e2), tf32r(e3));
        }
        __syncwarp();
        // PV: O[16x32] += P[16x64] @ V[64x32]
        const float* Pr0 = sm + SM_P + (16*w+gq)*PSTR + gj;
        #pragma unroll
        for (int kc = 0; kc < 8; kc++) {
            unsigned pa[4];
            pa[0] = __float_as_uint(Pr0[kc*8]);
            pa[1] = __float_as_uint(Pr0[8*PSTR + kc*8]);
            pa[2] = __float_as_uint(Pr0[kc*8 + 4]);
            pa[3] = __float_as_uint(Pr0[8*PSTR + kc*8 + 4]);
            const float* vr = sm + SM_V + (kc*4+gj)*VSTR + gq*2;
            #pragma unroll
            for (int n = 0; n < 4; n++) {
                uint2 vb = *reinterpret_cast<const uint2*>(vr + 16*n);
                unsigned bb[2] = {vb.x, vb.y};
                mma_tf32(O[n], pa, bb);
            }
        }
    }
    // row sums: reduce over the 4 lanes of each quad
    la += __shfl_xor_sync(0xffffffffu, la, 1);
    la += __shfl_xor_sync(0xffffffffu, la, 2);
    lb += __shfl_xor_sync(0xffffffffu, lb, 1);
    lb += __shfl_xor_sync(0xffffffffu, lb, 2);
    int row0 = qbase + 16*w + gq;
    float* dst = g_Pacc + ((size_t)(b*SPL + s)*NCc)*CIc;
    #pragma unroll
    for (int n = 0; n < 4; n++) {
        int col = 8*n + 2*gj;
        *reinterpret_cast<float2*>(dst + (size_t)row0*32 + col) =
            make_float2(O[n][0], O[n][1]);
        *reinterpret_cast<float2*>(dst + (size_t)(row0+8)*32 + col) =
            make_float2(O[n][2], O[n][3]);
    }
    if (gj == 0) {
        g_Pl[(size_t)(b*SPL + s)*NCc + row0]     = la;
        g_Pl[(size_t)(b*SPL + s)*NCc + row0 + 8] = lb;
    }
}

// Merge split-K partials, normalize, apply W (1x1 conv 32->64), coalesced
// channel-major write, BN batch stats.
__global__ void reduce_conv_k(const float* __restrict__ ww, const float* __restrict__ wb) {
    __shared__ float sw[Cc*CIc];
    __shared__ float stage[Cc*129];
    int tid = threadIdx.x;
    for (int i = tid; i < Cc*CIc; i += 128) sw[i] = ww[i];
    __syncthreads();
    int pix = blockIdx.x*128 + tid;
    int b = pix >> 12;
    int n = pix & (NCc-1);

    float a[CIc];
    #pragma unroll
    for (int c = 0; c < CIc; c++) a[c] = 0.f;
    float l = 0.f;
    #pragma unroll
    for (int s = 0; s < SPL; s++) {
        const float4* pa = reinterpret_cast<const float4*>(
            g_Pacc + ((size_t)((b*SPL+s)*NCc + n))*CIc);
        #pragma unroll
        for (int u = 0; u < 8; u++) {
            float4 v = pa[u];
            a[4*u+0] += v.x; a[4*u+1] += v.y; a[4*u+2] += v.z; a[4*u+3] += v.w;
        }
        l += g_Pl[(size_t)(b*SPL+s)*NCc + n];
    }
    float inv = 1.f/l;
    #pragma unroll
    for (int c = 0; c < CIc; c++) a[c] *= inv;

    for (int o = 0; o < Cc; o++) {
        float t = wb[o];
        #pragma unroll
        for (int c = 0; c < CIc; c++) t += sw[o*CIc+c]*a[c];
        stage[o*129 + tid] = t;
    }
    __syncthreads();
    int pblock = (blockIdx.x*128) & (NCc-1);
    float* vout = g_vconv + (size_t)b*Cc*NCc + pblock;
    for (int idx = tid; idx < Cc*128; idx += 128) {
        int o = idx >> 7, pl = idx & 127;
        vout[(size_t)o*NCc + pl] = stage[o*129 + pl];
    }
    if (tid < Cc) {
        float s1 = 0.f, s2 = 0.f;
        for (int pl = 0; pl < 128; pl++) {
            float v = stage[tid*129 + pl];
            s1 += v; s2 += v*v;
        }
        atomicAdd(&g_stats[tid], s1);
        atomicAdd(&g_stats[Cc+tid], s2);
    }
}

__global__ void finalize_k(const float* __restrict__ gamma, const float* __restrict__ beta) {
    int o = threadIdx.x;
    if (o < Cc) {
        float ninv = 1.f/(float)(Bn*NCc);
        float mean = g_stats[o]*ninv;
        float var  = g_stats[Cc+o]*ninv - mean*mean;
        float sc   = gamma[o]*rsqrtf(var + 1e-5f);
        g_ss[o]    = sc;
        g_ss[Cc+o] = beta[o] - mean*sc;
    }
}

// BN folded into upsample: out = sc*bilerp(vconv) + sh + main
__global__ void upsample_k(const float* __restrict__ mainf, float* __restrict__ out) {
    int idx = blockIdx.x*256 + threadIdx.x;
    int j = idx & 127, i = (idx >> 7) & 127, o = (idx >> 14) & 63, b = idx >> 20;
    float si = fminf(fmaxf((i+0.5f)*0.5f - 0.5f, 0.f), 63.f);
    float sj = fminf(fmaxf((j+0.5f)*0.5f - 0.5f, 0.f), 63.f);
    int i0 = (int)si; int i1 = min(i0+1, 63); float wi = si - (float)i0;
    int j0 = (int)sj; int j1 = min(j0+1, 63); float wj = sj - (float)j0;
    const float* vb = g_vconv + ((size_t)(b*Cc + o))*NCc;
    float v00 = vb[i0*64 + j0], v01 = vb[i0*64 + j1];
    float v10 = vb[i1*64 + j0], v11 = vb[i1*64 + j1];
    float v = (v00*(1.f-wj) + v01*wj)*(1.f-wi) + (v10*(1.f-wj) + v11*wj)*wi;
    out[idx] = v*g_ss[o] + g_ss[Cc+o] + mainf[idx];
}

extern "C" void kernel_launch(void* const* d_in, const int* in_sizes, int n_in,
                              void* d_out, int out_size) {
    const float* mainf   = (const float*)d_in[0];
    const float* crossf  = (const float*)d_in[1];
    const float* g_w     = (const float*)d_in[2];
    const float* g_b     = (const float*)d_in[3];
    const float* theta_w = (const float*)d_in[4];
    const float* theta_b = (const float*)d_in[5];
    const float* phi_w   = (const float*)d_in[6];
    const float* phi_b   = (const float*)d_in[7];
    const float* w_w     = (const float*)d_in[8];
    const float* w_b     = (const float*)d_in[9];
    const float* bn_g    = (const float*)d_in[10];
    const float* bn_b    = (const float*)d_in[11];
    float* out = (float*)d_out;

    cudaFuncSetAttribute(attn_tc_k, cudaFuncAttributeMaxDynamicSharedMemorySize, ATTN_SMEM);

    zero_k<<<1, 128>>>();
    proj_cross_k<<<Bn*NCc/128, 128>>>(crossf, g_w, g_b, theta_w, theta_b);
    proj_main_k<<<Bn*NCc/128, 128>>>(mainf, phi_w, phi_b);
    attn_tc_k<<<dim3(NCc/128, SPL, Bn), 256, ATTN_SMEM>>>();
    reduce_conv_k<<<Bn*NCc/128, 128>>>(w_w, w_b);
    finalize_k<<<1, 64>>>(bn_g, bn_b);
    upsample_k<<<(Bn*Cc*HMc*HMc)/256, 256>>>(mainf, out);
}

// round 15
// speedup vs baseline: 1.9523x; 1.2495x over previous
#include <cuda_runtime.h>
#include <cstdint>

#define Bn   4
#define Cc   64
#define CIc  32
#define HMc  128
#define NCc  4096
#define SPL  2          // split-K factor
#define TK   64         // keys per tile

typedef unsigned long long u64;

// ---------------- helpers ----------------------------------------------------
__device__ __forceinline__ float tf32r(float x) {
    unsigned u; asm("cvt.rna.tf32.f32 %0, %1;" : "=r"(u) : "f"(x));
    return __uint_as_float(u);
}
__device__ __forceinline__ u64 fma2(u64 a, u64 b, u64 c) {
    u64 d;
    asm("fma.rn.f32x2 %0, %1, %2, %3;" : "=l"(d) : "l"(a), "l"(b), "l"(c));
    return d;
}
__device__ __forceinline__ u64 pk2(float x, float y) {
    u64 r;
    asm("mov.b64 %0, {%1, %2};" : "=l"(r) : "f"(x), "f"(y));
    return r;
}
__device__ __forceinline__ void upk2(u64 v, float& x, float& y) {
    asm("mov.b64 {%0, %1}, %2;" : "=f"(x), "=f"(y) : "l"(v));
}
// D += A*B, m16n8k8 tf32 (A row-major, B col-major)
__device__ __forceinline__ void mma_tf32(float* d, const unsigned* a, const unsigned* b) {
    asm volatile("mma.sync.aligned.m16n8k8.row.col.f32.tf32.tf32.f32 "
        "{%0,%1,%2,%3}, {%4,%5,%6,%7}, {%8,%9}, {%0,%1,%2,%3};"
        : "+f"(d[0]), "+f"(d[1]), "+f"(d[2]), "+f"(d[3])
        : "r"(a[0]), "r"(a[1]), "r"(a[2]), "r"(a[3]), "r"(b[0]), "r"(b[1]));
}

// ---------------- scratch globals (no allocation allowed) --------------------
__device__ float g_Q[Bn*NCc*CIc];
__device__ float g_K[Bn*NCc*CIc];
__device__ float g_V[Bn*NCc*CIc];
__device__ float g_Pacc[Bn*SPL*NCc*CIc];   // unnormalized split-K partial O
__device__ float g_Pl[Bn*SPL*NCc];         // split-K partial row sums
__device__ float g_vconv[Bn*Cc*NCc];
__device__ float g_stats[2*Cc];
__device__ float g_ss[2*Cc];

__global__ void zero_k() {
    if (threadIdx.x < 2*Cc) g_stats[threadIdx.x] = 0.f;
}

// g(cross) -> Q, theta(cross) -> K  (tf32-rounded, [b*Nc+p][32] rows)
// Packed f32x2 math: weights pre-paired over output channels, [c][o2] layout.
__global__ void proj_cross_k(const float* __restrict__ cross,
                             const float* __restrict__ gw, const float* __restrict__ gb,
                             const float* __restrict__ tw, const float* __restrict__ tb) {
    __shared__ u64 swg2[Cc*16];   // [c][o2]  8 KB
    __shared__ u64 swt2[Cc*16];
    int tid = threadIdx.x;
    for (int i = tid; i < Cc*16; i += 128) {
        int c = i >> 4, o2 = i & 15;
        swg2[i] = pk2(gw[(2*o2)*Cc + c], gw[(2*o2+1)*Cc + c]);
        swt2[i] = pk2(tw[(2*o2)*Cc + c], tw[(2*o2+1)*Cc + c]);
    }
    __syncthreads();
    int pix = blockIdx.x*128 + tid;
    int b = pix >> 12, p = pix & (NCc-1);
    u64 q2[16], k2[16];
    #pragma unroll
    for (int o2 = 0; o2 < 16; o2++) {
        q2[o2] = pk2(gb[2*o2], gb[2*o2+1]);
        k2[o2] = pk2(tb[2*o2], tb[2*o2+1]);
    }
    const float* cp = cross + (size_t)b*Cc*NCc + p;
    for (int c = 0; c < Cc; c++) {
        float v = cp[(size_t)c*NCc];
        u64 vp = pk2(v, v);
        const u64* wg = swg2 + c*16;
        const u64* wt = swt2 + c*16;
        #pragma unroll
        for (int o2 = 0; o2 < 16; o2++) {
            q2[o2] = fma2(wg[o2], vp, q2[o2]);
            k2[o2] = fma2(wt[o2], vp, k2[o2]);
        }
    }
    float* qo = g_Q + (size_t)pix*CIc;
    float* ko = g_K + (size_t)pix*CIc;
    #pragma unroll
    for (int o2 = 0; o2 < 16; o2++) {
        float x, y;
        upk2(q2[o2], x, y); qo[2*o2] = tf32r(x); qo[2*o2+1] = tf32r(y);
        upk2(k2[o2], x, y); ko[2*o2] = tf32r(x); ko[2*o2+1] = tf32r(y);
    }
}

// phi(bilinear-downsample(main)) -> V (tf32-rounded).  128->64 == exact 2x2 mean.
__global__ void proj_main_k(const float* __restrict__ mainf,
                            const float* __restrict__ pw, const float* __restrict__ pb) {
    __shared__ u64 swp2[Cc*16];   // [c][o2]
    int tid = threadIdx.x;
    for (int i = tid; i < Cc*16; i += 128) {
        int c = i >> 4, o2 = i & 15;
        swp2[i] = pk2(pw[(2*o2)*Cc + c], pw[(2*o2+1)*Cc + c]);
    }
    __syncthreads();
    int pix = blockIdx.x*128 + tid;
    int b = pix >> 12, p = pix & (NCc-1);
    int i = p >> 6, j = p & 63;
    u64 a2[16];
    #pragma unroll
    for (int o2 = 0; o2 < 16; o2++) a2[o2] = pk2(pb[2*o2], pb[2*o2+1]);
    const float* mp = mainf + (size_t)b*Cc*HMc*HMc + (2*i)*HMc + 2*j;
    for (int c = 0; c < Cc; c++) {
        const float* m = mp + (size_t)c*HMc*HMc;
        float v = 0.25f*(m[0] + m[1] + m[HMc] + m[HMc+1]);
        u64 vp = pk2(v, v);
        const u64* wp = swp2 + c*16;
        #pragma unroll
        for (int o2 = 0; o2 < 16; o2++) a2[o2] = fma2(wp[o2], vp, a2[o2]);
    }
    float* vo = g_V + (size_t)pix*CIc;
    #pragma unroll
    for (int o2 = 0; o2 < 16; o2++) {
        float x, y;
        upk2(a2[o2], x, y);
        vo[2*o2] = tf32r(x); vo[2*o2+1] = tf32r(y);
    }
}

// ---------------- tensor-core attention (mma.sync tf32) ----------------------
// CTA = 128-query tile x split x batch; 8 warps x 16-row strips; TK=64 keys/tile.
// 2 CTAs/SM; split-K=2 => 256 CTAs. Register prefetch of next K/V tile hides
// global latency behind the QK/exp/PV compute phase.
// smem word-offset layout (fragment-paired, conflict-free strides):
#define KSTR 40
#define VSTR 72
#define PSTR 68
#define SM_K 0
#define SM_V (TK*KSTR)                  // 2560
#define SM_P (SM_V + 32*VSTR)           // 4864
#define ATTN_SMEM ((SM_P + 128*PSTR)*4) // 54272 bytes

__global__ void __launch_bounds__(256, 2) attn_tc_k() {
    extern __shared__ float sm[];
    int tid = threadIdx.x, lane = tid & 31, w = tid >> 5;
    int gq = lane >> 2, gj = lane & 3;
    int b = blockIdx.z, s = blockIdx.y, qbase = blockIdx.x*128;

    // Q fragments: rows 16w+gq, 16w+gq+8; 4 k-chunks of 8
    unsigned qa[4][4];
    {
        const float* Qb = g_Q + ((size_t)(b*NCc + qbase + 16*w))*CIc;
        #pragma unroll
        for (int kc = 0; kc < 4; kc++) {
            qa[kc][0] = __float_as_uint(Qb[gq*32     + 8*kc + gj]);
            qa[kc][1] = __float_as_uint(Qb[(gq+8)*32 + 8*kc + gj]);
            qa[kc][2] = __float_as_uint(Qb[gq*32     + 8*kc + gj + 4]);
            qa[kc][3] = __float_as_uint(Qb[(gq+8)*32 + 8*kc + gj + 4]);
        }
    }

    float O[4][4];
    #pragma unroll
    for (int n = 0; n < 4; n++) { O[n][0]=O[n][1]=O[n][2]=O[n][3]=0.f; }
    float la = 0.f, lb = 0.f;

    int r = tid >> 2, q4 = tid & 3;   // fill: key row r, column quarter q4
    int keybase = b*NCc + s*(NCc/SPL);
    const int NT = (NCc/SPL)/TK;

    // prefetch tile 0
    float4 pk0, pk1, pv0, pv1;
    {
        const float4* ks = reinterpret_cast<const float4*>(
            g_K + ((size_t)(keybase + r))*CIc);
        const float4* vs = reinterpret_cast<const float4*>(
            g_V + ((size_t)(keybase + r))*CIc);
        pk0 = ks[q4*2]; pk1 = ks[q4*2+1];
        pv0 = vs[q4*2]; pv1 = vs[q4*2+1];
    }

    for (int t = 0; t < NT; t++) {
        __syncthreads();   // previous tile fully consumed
        // K tile -> fragment-paired: K'[key][kc*8 + (c&3)*2 + ((c&7)>>2)]
        // V tile -> key-paired:      V'[(kc*4+gjv)][ch*2 + (key&7)>>2]
        {
            int vbase = SM_V + ((r>>3)*4 + (r&3))*VSTR + ((r&7)>>2);
            float kv0[4] = {pk0.x, pk0.y, pk0.z, pk0.w};
            float kv1[4] = {pk1.x, pk1.y, pk1.z, pk1.w};
            #pragma unroll
            for (int u = 0; u < 4; u++) {
                int c0 = q4*8 + u, c1 = q4*8 + 4 + u;
                sm[SM_K + r*KSTR + (c0>>3)*8 + (c0&3)*2 + ((c0&7)>>2)] = kv0[u];
                sm[SM_K + r*KSTR + (c1>>3)*8 + (c1&3)*2 + ((c1&7)>>2)] = kv1[u];
            }
            int c0 = q4*8;
            sm[vbase + (c0+0)*2] = pv0.x;
            sm[vbase + (c0+1)*2] = pv0.y;
            sm[vbase + (c0+2)*2] = pv0.z;
            sm[vbase + (c0+3)*2] = pv0.w;
            sm[vbase + (c0+4)*2] = pv1.x;
            sm[vbase + (c0+5)*2] = pv1.y;
            sm[vbase + (c0+6)*2] = pv1.z;
            sm[vbase + (c0+7)*2] = pv1.w;
        }
        // prefetch next tile (overlaps the whole compute phase below)
        if (t + 1 < NT) {
            const float4* ks = reinterpret_cast<const float4*>(
                g_K + ((size_t)(keybase + (t+1)*TK + r))*CIc);
            const float4* vs = reinterpret_cast<const float4*>(
                g_V + ((size_t)(keybase + (t+1)*TK + r))*CIc);
            pk0 = ks[q4*2]; pk1 = ks[q4*2+1];
            pv0 = vs[q4*2]; pv1 = vs[q4*2+1];
        }
        __syncthreads();

        // QK: 8 n-tiles of 8 keys, k = 32 (4 chunks)
        float S[8][4];
        #pragma unroll
        for (int n = 0; n < 8; n++) {
            S[n][0]=S[n][1]=S[n][2]=S[n][3]=0.f;
            const float* kr = sm + SM_K + (8*n + gq)*KSTR + gj*2;
            #pragma unroll
            for (int kc = 0; kc < 4; kc++) {
                uint2 kb = *reinterpret_cast<const uint2*>(kr + kc*8);
                unsigned bb[2] = {kb.x, kb.y};
                mma_tf32(S[n], qa[kc], bb);
            }
        }
        // exp + warp-private P store
        #pragma unroll
        for (int n = 0; n < 8; n++) {
            float e0 = __expf(S[n][0]), e1 = __expf(S[n][1]);
            float e2 = __expf(S[n][2]), e3 = __expf(S[n][3]);
            la += e0 + e1; lb += e2 + e3;
            int col = 8*n + 2*gj;
            *reinterpret_cast<float2*>(sm + SM_P + (16*w+gq)*PSTR + col) =
                make_float2(tf32r(e0), tf32r(e1));
            *reinterpret_cast<float2*>(sm + SM_P + (16*w+gq+8)*PSTR + col) =
                make_float2(tf32r(e2), tf32r(e3));
        }
        __syncwarp();
        // PV: O[16x32] += P[16x64] @ V[64x32]
        const float* Pr0 = sm + SM_P + (16*w+gq)*PSTR + gj;
        #pragma unroll
        for (int kc = 0; kc < 8; kc++) {
            unsigned pa[4];
            pa[0] = __float_as_uint(Pr0[kc*8]);
            pa[1] = __float_as_uint(Pr0[8*PSTR + kc*8]);
            pa[2] = __float_as_uint(Pr0[kc*8 + 4]);
            pa[3] = __float_as_uint(Pr0[8*PSTR + kc*8 + 4]);
            const float* vr = sm + SM_V + (kc*4+gj)*VSTR + gq*2;
            #pragma unroll
            for (int n = 0; n < 4; n++) {
                uint2 vb = *reinterpret_cast<const uint2*>(vr + 16*n);
                unsigned bb[2] = {vb.x, vb.y};
                mma_tf32(O[n], pa, bb);
            }
        }
    }
    // row sums: reduce over the 4 lanes of each quad
    la += __shfl_xor_sync(0xffffffffu, la, 1);
    la += __shfl_xor_sync(0xffffffffu, la, 2);
    lb += __shfl_xor_sync(0xffffffffu, lb, 1);
    lb += __shfl_xor_sync(0xffffffffu, lb, 2);
    int row0 = qbase + 16*w + gq;
    float* dst = g_Pacc + ((size_t)(b*SPL + s)*NCc)*CIc;
    #pragma unroll
    for (int n = 0; n < 4; n++) {
        int col = 8*n + 2*gj;
        *reinterpret_cast<float2*>(dst + (size_t)row0*32 + col) =
            make_float2(O[n][0], O[n][1]);
        *reinterpret_cast<float2*>(dst + (size_t)(row0+8)*32 + col) =
            make_float2(O[n][2], O[n][3]);
    }
    if (gj == 0) {
        g_Pl[(size_t)(b*SPL + s)*NCc + row0]     = la;
        g_Pl[(size_t)(b*SPL + s)*NCc + row0 + 8] = lb;
    }
}

// Merge split-K partials, normalize, apply W (packed f32x2 1x1 conv 32->64),
// coalesced channel-major write, BN batch stats.
__global__ void reduce_conv_k(const float* __restrict__ ww, const float* __restrict__ wb) {
    __shared__ u64 sw2[CIc*Cc/2];      // [c][o2], o2=0..31  8 KB
    __shared__ float stage[Cc*129];    // 33 KB, padded
    int tid = threadIdx.x;
    for (int i = tid; i < CIc*Cc/2; i += 128) {
        int c = i >> 5, o2 = i & 31;
        sw2[i] = pk2(ww[(2*o2)*CIc + c], ww[(2*o2+1)*CIc + c]);
    }
    __syncthreads();
    int pix = blockIdx.x*128 + tid;
    int b = pix >> 12;
    int n = pix & (NCc-1);

    float a[CIc];
    #pragma unroll
    for (int c = 0; c < CIc; c++) a[c] = 0.f;
    float l = 0.f;
    #pragma unroll
    for (int s = 0; s < SPL; s++) {
        const float4* pa = reinterpret_cast<const float4*>(
            g_Pacc + ((size_t)((b*SPL+s)*NCc + n))*CIc);
        #pragma unroll
        for (int u = 0; u < 8; u++) {
            float4 v = pa[u];
            a[4*u+0] += v.x; a[4*u+1] += v.y; a[4*u+2] += v.z; a[4*u+3] += v.w;
        }
        l += g_Pl[(size_t)(b*SPL+s)*NCc + n];
    }
    float inv = 1.f/l;
    #pragma unroll
    for (int c = 0; c < CIc; c++) a[c] *= inv;

    u64 acc2[32];
    #pragma unroll
    for (int o2 = 0; o2 < 32; o2++) acc2[o2] = pk2(wb[2*o2], wb[2*o2+1]);
    for (int c = 0; c < CIc; c++) {
        u64 ap = pk2(a[c], a[c]);
        const u64* wr = sw2 + c*32;
        #pragma unroll
        for (int o2 = 0; o2 < 32; o2++) acc2[o2] = fma2(wr[o2], ap, acc2[o2]);
    }
    #pragma unroll
    for (int o2 = 0; o2 < 32; o2++) {
        float x, y;
        upk2(acc2[o2], x, y);
        stage[(2*o2)*129 + tid]   = x;
        stage[(2*o2+1)*129 + tid] = y;
    }
    __syncthreads();
    int pblock = (blockIdx.x*128) & (NCc-1);
    float* vout = g_vconv + (size_t)b*Cc*NCc + pblock;
    for (int idx = tid; idx < Cc*128; idx += 128) {
        int o = idx >> 7, pl = idx & 127;
        vout[(size_t)o*NCc + pl] = stage[o*129 + pl];
    }
    if (tid < Cc) {
        float s1 = 0.f, s2 = 0.f;
        for (int pl = 0; pl < 128; pl++) {
            float v = stage[tid*129 + pl];
            s1 += v; s2 += v*v;
        }
        atomicAdd(&g_stats[tid], s1);
        atomicAdd(&g_stats[Cc+tid], s2);
    }
}

__global__ void finalize_k(const float* __restrict__ gamma, const float* __restrict__ beta) {
    int o = threadIdx.x;
    if (o < Cc) {
        float ninv = 1.f/(float)(Bn*NCc);
        float mean = g_stats[o]*ninv;
        float var  = g_stats[Cc+o]*ninv - mean*mean;
        float sc   = gamma[o]*rsqrtf(var + 1e-5f);
        g_ss[o]    = sc;
        g_ss[Cc+o] = beta[o] - mean*sc;
    }
}

// BN folded into upsample: out = sc*bilerp(vconv) + sh + main
__global__ void upsample_k(const float* __restrict__ mainf, float* __restrict__ out) {
    int idx = blockIdx.x*256 + threadIdx.x;
    int j = idx & 127, i = (idx >> 7) & 127, o = (idx >> 14) & 63, b = idx >> 20;
    float si = fminf(fmaxf((i+0.5f)*0.5f - 0.5f, 0.f), 63.f);
    float sj = fminf(fmaxf((j+0.5f)*0.5f - 0.5f, 0.f), 63.f);
    int i0 = (int)si; int i1 = min(i0+1, 63); float wi = si - (float)i0;
    int j0 = (int)sj; int j1 = min(j0+1, 63); float wj = sj - (float)j0;
    const float* vb = g_vconv + ((size_t)(b*Cc + o))*NCc;
    float v00 = vb[i0*64 + j0], v01 = vb[i0*64 + j1];
    float v10 = vb[i1*64 + j0], v11 = vb[i1*64 + j1];
    float v = (v00*(1.f-wj) + v01*wj)*(1.f-wi) + (v10*(1.f-wj) + v11*wj)*wi;
    out[idx] = v*g_ss[o] + g_ss[Cc+o] + mainf[idx];
}

extern "C" void kernel_launch(void* const* d_in, const int* in_sizes, int n_in,
                              void* d_out, int out_size) {
    const float* mainf   = (const float*)d_in[0];
    const float* crossf  = (const float*)d_in[1];
    const float* g_w     = (const float*)d_in[2];
    const float* g_b     = (const float*)d_in[3];
    const float* theta_w = (const float*)d_in[4];
    const float* theta_b = (const float*)d_in[5];
    const float* phi_w   = (const float*)d_in[6];
    const float* phi_b   = (const float*)d_in[7];
    const float* w_w     = (const float*)d_in[8];
    const float* w_b     = (const float*)d_in[9];
    const float* bn_g    = (const float*)d_in[10];
    const float* bn_b    = (const float*)d_in[11];
    float* out = (float*)d_out;

    cudaFuncSetAttribute(attn_tc_k, cudaFuncAttributeMaxDynamicSharedMemorySize, ATTN_SMEM);

    zero_k<<<1, 128>>>();
    proj_cross_k<<<Bn*NCc/128, 128>>>(crossf, g_w, g_b, theta_w, theta_b);
    proj_main_k<<<Bn*NCc/128, 128>>>(mainf, phi_w, phi_b);
    attn_tc_k<<<dim3(NCc/128, SPL, Bn), 256, ATTN_SMEM>>>();
    reduce_conv_k<<<Bn*NCc/128, 128>>>(w_w, w_b);
    finalize_k<<<1, 64>>>(bn_g, bn_b);
    upsample_k<<<(Bn*Cc*HMc*HMc)/256, 256>>>(mainf, out);
}

// round 16
// speedup vs baseline: 2.0461x; 1.0481x over previous
#include <cuda_runtime.h>
#include <cstdint>

#define Bn   4
#define Cc   64
#define CIc  32
#define HMc  128
#define NCc  4096
#define SPL  4          // split-K factor
#define TK   64         // keys per tile

typedef unsigned long long u64;

// ---------------- helpers ----------------------------------------------------
__device__ __forceinline__ float tf32r(float x) {
    unsigned u; asm("cvt.rna.tf32.f32 %0, %1;" : "=r"(u) : "f"(x));
    return __uint_as_float(u);
}
__device__ __forceinline__ u64 fma2(u64 a, u64 b, u64 c) {
    u64 d;
    asm("fma.rn.f32x2 %0, %1, %2, %3;" : "=l"(d) : "l"(a), "l"(b), "l"(c));
    return d;
}
__device__ __forceinline__ u64 pk2(float x, float y) {
    u64 r;
    asm("mov.b64 %0, {%1, %2};" : "=l"(r) : "f"(x), "f"(y));
    return r;
}
__device__ __forceinline__ void upk2(u64 v, float& x, float& y) {
    asm("mov.b64 {%0, %1}, %2;" : "=f"(x), "=f"(y) : "l"(v));
}
// D += A*B, m16n8k8 tf32 (A row-major, B col-major)
__device__ __forceinline__ void mma_tf32(float* d, const unsigned* a, const unsigned* b) {
    asm volatile("mma.sync.aligned.m16n8k8.row.col.f32.tf32.tf32.f32 "
        "{%0,%1,%2,%3}, {%4,%5,%6,%7}, {%8,%9}, {%0,%1,%2,%3};"
        : "+f"(d[0]), "+f"(d[1]), "+f"(d[2]), "+f"(d[3])
        : "r"(a[0]), "r"(a[1]), "r"(a[2]), "r"(a[3]), "r"(b[0]), "r"(b[1]));
}

// ---------------- scratch globals (no allocation allowed) --------------------
__device__ float g_Q[Bn*NCc*CIc];
__device__ float g_K[Bn*NCc*CIc];
__device__ float g_V[Bn*NCc*CIc];
__device__ float g_Pacc[Bn*SPL*NCc*CIc];   // unnormalized split-K partial O
__device__ float g_Pl[Bn*SPL*NCc];         // split-K partial row sums
__device__ float g_vconv[Bn*Cc*NCc];
__device__ float g_stats[2*Cc];
__device__ float g_ss[2*Cc];

__global__ void zero_k() {
    if (threadIdx.x < 2*Cc) g_stats[threadIdx.x] = 0.f;
}

// g(cross) -> Q, theta(cross) -> K  (tf32-rounded, [b*Nc+p][32] rows)
// Packed f32x2 math: weights pre-paired over output channels, [c][o2] layout.
__global__ void proj_cross_k(const float* __restrict__ cross,
                             const float* __restrict__ gw, const float* __restrict__ gb,
                             const float* __restrict__ tw, const float* __restrict__ tb) {
    __shared__ u64 swg2[Cc*16];   // [c][o2]  8 KB
    __shared__ u64 swt2[Cc*16];
    int tid = threadIdx.x;
    for (int i = tid; i < Cc*16; i += 128) {
        int c = i >> 4, o2 = i & 15;
        swg2[i] = pk2(gw[(2*o2)*Cc + c], gw[(2*o2+1)*Cc + c]);
        swt2[i] = pk2(tw[(2*o2)*Cc + c], tw[(2*o2+1)*Cc + c]);
    }
    __syncthreads();
    int pix = blockIdx.x*128 + tid;
    int b = pix >> 12, p = pix & (NCc-1);
    u64 q2[16], k2[16];
    #pragma unroll
    for (int o2 = 0; o2 < 16; o2++) {
        q2[o2] = pk2(gb[2*o2], gb[2*o2+1]);
        k2[o2] = pk2(tb[2*o2], tb[2*o2+1]);
    }
    const float* cp = cross + (size_t)b*Cc*NCc + p;
    for (int c = 0; c < Cc; c++) {
        float v = cp[(size_t)c*NCc];
        u64 vp = pk2(v, v);
        const u64* wg = swg2 + c*16;
        const u64* wt = swt2 + c*16;
        #pragma unroll
        for (int o2 = 0; o2 < 16; o2++) {
            q2[o2] = fma2(wg[o2], vp, q2[o2]);
            k2[o2] = fma2(wt[o2], vp, k2[o2]);
        }
    }
    float* qo = g_Q + (size_t)pix*CIc;
    float* ko = g_K + (size_t)pix*CIc;
    #pragma unroll
    for (int o2 = 0; o2 < 16; o2++) {
        float x, y;
        upk2(q2[o2], x, y); qo[2*o2] = tf32r(x); qo[2*o2+1] = tf32r(y);
        upk2(k2[o2], x, y); ko[2*o2] = tf32r(x); ko[2*o2+1] = tf32r(y);
    }
}

// phi(bilinear-downsample(main)) -> V (tf32-rounded).  128->64 == exact 2x2 mean.
__global__ void proj_main_k(const float* __restrict__ mainf,
                            const float* __restrict__ pw, const float* __restrict__ pb) {
    __shared__ u64 swp2[Cc*16];   // [c][o2]
    int tid = threadIdx.x;
    for (int i = tid; i < Cc*16; i += 128) {
        int c = i >> 4, o2 = i & 15;
        swp2[i] = pk2(pw[(2*o2)*Cc + c], pw[(2*o2+1)*Cc + c]);
    }
    __syncthreads();
    int pix = blockIdx.x*128 + tid;
    int b = pix >> 12, p = pix & (NCc-1);
    int i = p >> 6, j = p & 63;
    u64 a2[16];
    #pragma unroll
    for (int o2 = 0; o2 < 16; o2++) a2[o2] = pk2(pb[2*o2], pb[2*o2+1]);
    const float* mp = mainf + (size_t)b*Cc*HMc*HMc + (2*i)*HMc + 2*j;
    for (int c = 0; c < Cc; c++) {
        const float* m = mp + (size_t)c*HMc*HMc;
        float v = 0.25f*(m[0] + m[1] + m[HMc] + m[HMc+1]);
        u64 vp = pk2(v, v);
        const u64* wp = swp2 + c*16;
        #pragma unroll
        for (int o2 = 0; o2 < 16; o2++) a2[o2] = fma2(wp[o2], vp, a2[o2]);
    }
    float* vo = g_V + (size_t)pix*CIc;
    #pragma unroll
    for (int o2 = 0; o2 < 16; o2++) {
        float x, y;
        upk2(a2[o2], x, y);
        vo[2*o2] = tf32r(x); vo[2*o2+1] = tf32r(y);
    }
}

// ---------------- tensor-core attention (mma.sync tf32, M=32/warp) -----------
// CTA = 128-query tile x split x batch; 4 warps x 32-row strips; TK=64 keys/tile.
// Every K/V B-fragment feeds TWO m-tiles (halves smem B traffic vs M=16).
// 4 CTAs/SM; SPL=4 => 512 CTAs (~0.86 waves). K register-prefetched.
// Per tile: per n-tile {S = Q@K^T (8 MMA), exp, P store}, then O += P@V.
// Unnormalized accumulation (logits O(1): no max), partials merged in reduce.
#define KSTR 40
#define VSTR 72
#define PSTR 68
#define SM_K 0
#define SM_V (TK*KSTR)                    // 2560
#define SM_P (SM_V + 32*VSTR)             // 4864
#define ATTN_SMEM ((SM_P + 128*PSTR)*4)   // 54272 bytes

__global__ void __launch_bounds__(128, 4) attn_tc_k() {
    extern __shared__ float sm[];
    int tid = threadIdx.x, lane = tid & 31, w = tid >> 5;
    int gq = lane >> 2, gj = lane & 3;
    int b = blockIdx.z, s = blockIdx.y, qbase = blockIdx.x*128;

    // Q fragments for 2 m-tiles: rows 32w + {gq, gq+8, gq+16, gq+24}
    unsigned qa[2][4][4];
    {
        const float* Qb = g_Q + ((size_t)(b*NCc + qbase + 32*w))*CIc;
        #pragma unroll
        for (int m = 0; m < 2; m++)
            #pragma unroll
            for (int kc = 0; kc < 4; kc++) {
                qa[m][kc][0] = __float_as_uint(Qb[(16*m+gq)*32   + 8*kc + gj]);
                qa[m][kc][1] = __float_as_uint(Qb[(16*m+gq+8)*32 + 8*kc + gj]);
                qa[m][kc][2] = __float_as_uint(Qb[(16*m+gq)*32   + 8*kc + gj + 4]);
                qa[m][kc][3] = __float_as_uint(Qb[(16*m+gq+8)*32 + 8*kc + gj + 4]);
            }
    }

    float O0[4][4], O1[4][4];
    #pragma unroll
    for (int n = 0; n < 4; n++) {
        O0[n][0]=O0[n][1]=O0[n][2]=O0[n][3]=0.f;
        O1[n][0]=O1[n][1]=O1[n][2]=O1[n][3]=0.f;
    }
    float la0 = 0.f, lb0 = 0.f, la1 = 0.f, lb1 = 0.f;

    int r = tid >> 1, h = tid & 1;       // fill: key row r, channel half h
    int keybase = b*NCc + s*(NCc/SPL);
    const int NT = (NCc/SPL)/TK;

    // prefetch K tile 0 (4 x LDG.128 = 16 channels of key r)
    float4 pk[4];
    {
        const float4* ks = reinterpret_cast<const float4*>(
            g_K + ((size_t)(keybase + r))*CIc + h*16);
        pk[0] = ks[0]; pk[1] = ks[1]; pk[2] = ks[2]; pk[3] = ks[3];
    }

    for (int t = 0; t < NT; t++) {
        __syncthreads();   // previous tile fully consumed
        // V tile load (not prefetched) + store, key-paired layout
        {
            const float4* vs = reinterpret_cast<const float4*>(
                g_V + ((size_t)(keybase + t*TK + r))*CIc + h*16);
            float vf[16];
            *reinterpret_cast<float4*>(&vf[0])  = vs[0];
            *reinterpret_cast<float4*>(&vf[4])  = vs[1];
            *reinterpret_cast<float4*>(&vf[8])  = vs[2];
            *reinterpret_cast<float4*>(&vf[12]) = vs[3];
            int vbase = SM_V + ((r>>3)*4 + (r&3))*VSTR + ((r&7)>>2);
            #pragma unroll
            for (int u = 0; u < 16; u++)
                sm[vbase + (16*h + u)*2] = vf[u];
        }
        // K store from prefetch, fragment-paired layout, 8 x STS.64
        {
            float kf[16];
            *reinterpret_cast<float4*>(&kf[0])  = pk[0];
            *reinterpret_cast<float4*>(&kf[4])  = pk[1];
            *reinterpret_cast<float4*>(&kf[8])  = pk[2];
            *reinterpret_cast<float4*>(&kf[12]) = pk[3];
            int kb_ = SM_K + r*KSTR;
            #pragma unroll
            for (int cc = 0; cc < 2; cc++)
                #pragma unroll
                for (int u = 0; u < 4; u++)
                    *reinterpret_cast<float2*>(&sm[kb_ + (2*h+cc)*8 + u*2]) =
                        make_float2(kf[8*cc + u], kf[8*cc + 4 + u]);
        }
        // prefetch next K tile
        if (t + 1 < NT) {
            const float4* ks = reinterpret_cast<const float4*>(
                g_K + ((size_t)(keybase + (t+1)*TK + r))*CIc + h*16);
            pk[0] = ks[0]; pk[1] = ks[1]; pk[2] = ks[2]; pk[3] = ks[3];
        }
        __syncthreads();

        // QK + exp + P store, per 8-key n-tile (S regs recycled each n)
        #pragma unroll
        for (int n = 0; n < 8; n++) {
            const float* kr = sm + SM_K + (8*n + gq)*KSTR + gj*2;
            uint2 kb[4];
            #pragma unroll
            for (int kc = 0; kc < 4; kc++)
                kb[kc] = *reinterpret_cast<const uint2*>(kr + kc*8);
            float S0[4] = {0.f,0.f,0.f,0.f};
            float S1[4] = {0.f,0.f,0.f,0.f};
            #pragma unroll
            for (int kc = 0; kc < 4; kc++) {
                unsigned bb[2] = {kb[kc].x, kb[kc].y};
                mma_tf32(S0, qa[0][kc], bb);
                mma_tf32(S1, qa[1][kc], bb);
            }
            float e00 = __expf(S0[0]), e01 = __expf(S0[1]);
            float e02 = __expf(S0[2]), e03 = __expf(S0[3]);
            float e10 = __expf(S1[0]), e11 = __expf(S1[1]);
            float e12 = __expf(S1[2]), e13 = __expf(S1[3]);
            la0 += e00 + e01; lb0 += e02 + e03;
            la1 += e10 + e11; lb1 += e12 + e13;
            float* pr = sm + SM_P + (32*w + gq)*PSTR + 8*n + 2*gj;
            *reinterpret_cast<float2*>(pr)            = make_float2(e00, e01);
            *reinterpret_cast<float2*>(pr +  8*PSTR)  = make_float2(e02, e03);
            *reinterpret_cast<float2*>(pr + 16*PSTR)  = make_float2(e10, e11);
            *reinterpret_cast<float2*>(pr + 24*PSTR)  = make_float2(e12, e13);
        }
        __syncwarp();
        // PV: O[32x32] += P[32x64] @ V[64x32]; each V frag feeds 2 m-tiles
        const float* Pr0 = sm + SM_P + (32*w + gq)*PSTR + gj;
        #pragma unroll
        for (int kc = 0; kc < 8; kc++) {
            unsigned pa0[4], pa1[4];
            pa0[0] = __float_as_uint(Pr0[kc*8]);
            pa0[1] = __float_as_uint(Pr0[8*PSTR  + kc*8]);
            pa0[2] = __float_as_uint(Pr0[kc*8 + 4]);
            pa0[3] = __float_as_uint(Pr0[8*PSTR  + kc*8 + 4]);
            pa1[0] = __float_as_uint(Pr0[16*PSTR + kc*8]);
            pa1[1] = __float_as_uint(Pr0[24*PSTR + kc*8]);
            pa1[2] = __float_as_uint(Pr0[16*PSTR + kc*8 + 4]);
            pa1[3] = __float_as_uint(Pr0[24*PSTR + kc*8 + 4]);
            const float* vr = sm + SM_V + (kc*4 + gj)*VSTR + gq*2;
            #pragma unroll
            for (int n = 0; n < 4; n++) {
                uint2 vb = *reinterpret_cast<const uint2*>(vr + 16*n);
                unsigned bb[2] = {vb.x, vb.y};
                mma_tf32(O0[n], pa0, bb);
                mma_tf32(O1[n], pa1, bb);
            }
        }
    }
    // row sums: reduce over the 4 lanes of each quad
    la0 += __shfl_xor_sync(0xffffffffu, la0, 1);
    la0 += __shfl_xor_sync(0xffffffffu, la0, 2);
    lb0 += __shfl_xor_sync(0xffffffffu, lb0, 1);
    lb0 += __shfl_xor_sync(0xffffffffu, lb0, 2);
    la1 += __shfl_xor_sync(0xffffffffu, la1, 1);
    la1 += __shfl_xor_sync(0xffffffffu, la1, 2);
    lb1 += __shfl_xor_sync(0xffffffffu, lb1, 1);
    lb1 += __shfl_xor_sync(0xffffffffu, lb1, 2);

    int row0 = qbase + 32*w + gq;
    float* dst = g_Pacc + ((size_t)(b*SPL + s)*NCc)*CIc;
    #pragma unroll
    for (int n = 0; n < 4; n++) {
        int col = 8*n + 2*gj;
        *reinterpret_cast<float2*>(dst + (size_t)row0*32 + col) =
            make_float2(O0[n][0], O0[n][1]);
        *reinterpret_cast<float2*>(dst + (size_t)(row0+8)*32 + col) =
            make_float2(O0[n][2], O0[n][3]);
        *reinterpret_cast<float2*>(dst + (size_t)(row0+16)*32 + col) =
            make_float2(O1[n][0], O1[n][1]);
        *reinterpret_cast<float2*>(dst + (size_t)(row0+24)*32 + col) =
            make_float2(O1[n][2], O1[n][3]);
    }
    if (gj == 0) {
        float* pl = g_Pl + (size_t)(b*SPL + s)*NCc;
        pl[row0]      = la0;
        pl[row0 + 8]  = lb0;
        pl[row0 + 16] = la1;
        pl[row0 + 24] = lb1;
    }
}

// Merge split-K partials, normalize, apply W (packed f32x2 1x1 conv 32->64),
// coalesced channel-major write, BN batch stats.
__global__ void reduce_conv_k(const float* __restrict__ ww, const float* __restrict__ wb) {
    __shared__ u64 sw2[CIc*Cc/2];      // [c][o2], o2=0..31  8 KB
    __shared__ float stage[Cc*129];    // 33 KB, padded
    int tid = threadIdx.x;
    for (int i = tid; i < CIc*Cc/2; i += 128) {
        int c = i >> 5, o2 = i & 31;
        sw2[i] = pk2(ww[(2*o2)*CIc + c], ww[(2*o2+1)*CIc + c]);
    }
    __syncthreads();
    int pix = blockIdx.x*128 + tid;
    int b = pix >> 12;
    int n = pix & (NCc-1);

    float a[CIc];
    #pragma unroll
    for (int c = 0; c < CIc; c++) a[c] = 0.f;
    float l = 0.f;
    #pragma unroll
    for (int s = 0; s < SPL; s++) {
        const float4* pa = reinterpret_cast<const float4*>(
            g_Pacc + ((size_t)((b*SPL+s)*NCc + n))*CIc);
        #pragma unroll
        for (int u = 0; u < 8; u++) {
            float4 v = pa[u];
            a[4*u+0] += v.x; a[4*u+1] += v.y; a[4*u+2] += v.z; a[4*u+3] += v.w;
        }
        l += g_Pl[(size_t)(b*SPL+s)*NCc + n];
    }
    float inv = 1.f/l;
    #pragma unroll
    for (int c = 0; c < CIc; c++) a[c] *= inv;

    u64 acc2[32];
    #pragma unroll
    for (int o2 = 0; o2 < 32; o2++) acc2[o2] = pk2(wb[2*o2], wb[2*o2+1]);
    for (int c = 0; c < CIc; c++) {
        u64 ap = pk2(a[c], a[c]);
        const u64* wr = sw2 + c*32;
        #pragma unroll
        for (int o2 = 0; o2 < 32; o2++) acc2[o2] = fma2(wr[o2], ap, acc2[o2]);
    }
    #pragma unroll
    for (int o2 = 0; o2 < 32; o2++) {
        float x, y;
        upk2(acc2[o2], x, y);
        stage[(2*o2)*129 + tid]   = x;
        stage[(2*o2+1)*129 + tid] = y;
    }
    __syncthreads();
    int pblock = (blockIdx.x*128) & (NCc-1);
    float* vout = g_vconv + (size_t)b*Cc*NCc + pblock;
    for (int idx = tid; idx < Cc*128; idx += 128) {
        int o = idx >> 7, pl = idx & 127;
        vout[(size_t)o*NCc + pl] = stage[o*129 + pl];
    }
    if (tid < Cc) {
        float s1 = 0.f, s2 = 0.f;
        for (int pl = 0; pl < 128; pl++) {
            float v = stage[tid*129 + pl];
            s1 += v; s2 += v*v;
        }
        atomicAdd(&g_stats[tid], s1);
        atomicAdd(&g_stats[Cc+tid], s2);
    }
}

__global__ void finalize_k(const float* __restrict__ gamma, const float* __restrict__ beta) {
    int o = threadIdx.x;
    if (o < Cc) {
        float ninv = 1.f/(float)(Bn*NCc);
        float mean = g_stats[o]*ninv;
        float var  = g_stats[Cc+o]*ninv - mean*mean;
        float sc   = gamma[o]*rsqrtf(var + 1e-5f);
        g_ss[o]    = sc;
        g_ss[Cc+o] = beta[o] - mean*sc;
    }
}

// BN folded into upsample: out = sc*bilerp(vconv) + sh + main
__global__ void upsample_k(const float* __restrict__ mainf, float* __restrict__ out) {
    int idx = blockIdx.x*256 + threadIdx.x;
    int j = idx & 127, i = (idx >> 7) & 127, o = (idx >> 14) & 63, b = idx >> 20;
    float si = fminf(fmaxf((i+0.5f)*0.5f - 0.5f, 0.f), 63.f);
    float sj = fminf(fmaxf((j+0.5f)*0.5f - 0.5f, 0.f), 63.f);
    int i0 = (int)si; int i1 = min(i0+1, 63); float wi = si - (float)i0;
    int j0 = (int)sj; int j1 = min(j0+1, 63); float wj = sj - (float)j0;
    const float* vb = g_vconv + ((size_t)(b*Cc + o))*NCc;
    float v00 = vb[i0*64 + j0], v01 = vb[i0*64 + j1];
    float v10 = vb[i1*64 + j0], v11 = vb[i1*64 + j1];
    float v = (v00*(1.f-wj) + v01*wj)*(1.f-wi) + (v10*(1.f-wj) + v11*wj)*wi;
    out[idx] = v*g_ss[o] + g_ss[Cc+o] + mainf[idx];
}

extern "C" void kernel_launch(void* const* d_in, const int* in_sizes, int n_in,
                              void* d_out, int out_size) {
    const float* mainf   = (const float*)d_in[0];
    const float* crossf  = (const float*)d_in[1];
    const float* g_w     = (const float*)d_in[2];
    const float* g_b     = (const float*)d_in[3];
    const float* theta_w = (const float*)d_in[4];
    const float* theta_b = (const float*)d_in[5];
    const float* phi_w   = (const float*)d_in[6];
    const float* phi_b   = (const float*)d_in[7];
    const float* w_w     = (const float*)d_in[8];
    const float* w_b     = (const float*)d_in[9];
    const float* bn_g    = (const float*)d_in[10];
    const float* bn_b    = (const float*)d_in[11];
    float* out = (float*)d_out;

    cudaFuncSetAttribute(attn_tc_k, cudaFuncAttributeMaxDynamicSharedMemorySize, ATTN_SMEM);

    zero_k<<<1, 128>>>();
    proj_cross_k<<<Bn*NCc/128, 128>>>(crossf, g_w, g_b, theta_w, theta_b);
    proj_main_k<<<Bn*NCc/128, 128>>>(mainf, phi_w, phi_b);
    attn_tc_k<<<dim3(NCc/128, SPL, Bn), 128, ATTN_SMEM>>>();
    reduce_conv_k<<<Bn*NCc/128, 128>>>(w_w, w_b);
    finalize_k<<<1, 64>>>(bn_g, bn_b);
    upsample_k<<<(Bn*Cc*HMc*HMc)/256, 256>>>(mainf, out);
}